// round 13
// baseline (speedup 1.0000x reference)
#include <cuda_runtime.h>
#include <cuda_bf16.h>
#include <math.h>

#define BSN 32
#define QN 1024
#define KN 96
#define QN1 (QN + 1)
#define INFV 1000000000.0f
#define NELEM (QN * 3)
#define NT 128
#define CPT 8
#define NPR (CPT / 2)
#define NW (NT / 32)
#define FINF __int_as_float(0x7F800000)

__device__ __forceinline__ bool probe_is_labels(const float* x) {
    const int qs[6] = {0, 13, 95, 96, 511, 1023};
    #pragma unroll
    for (int t = 0; t < 6; t++) {
        float v = x[qs[t] * 3];
        if (v != 0.0f && v != 1.0f) return false;
    }
    return true;
}

// Bit-exact replica of XLA:CPU GenerateVF32Exp (proven R6).
__device__ __forceinline__ float xla_cpu_expf(float x_in) {
    float x = fmaxf(fminf(x_in, 88.3762626647950f), -88.3762626647949f);
    float fx = floorf(__fmaf_rn(x, 1.44269504088896341f, 0.5f));
    float tmp = __fmul_rn(0.693359375f, fx);
    float z   = __fmul_rn(-2.12194440e-4f, fx);
    x = __fsub_rn(x, tmp);
    x = __fsub_rn(x, z);
    float x2 = __fmul_rn(x, x);
    float y = __fmaf_rn(x, 1.9875691500E-4f, 1.3981999507E-3f);
    y = __fmaf_rn(y, x, 8.3334519073E-3f);
    y = __fmaf_rn(y, x, 4.1665795894E-2f);
    y = __fmaf_rn(y, x, 1.6666665459E-1f);
    y = __fmaf_rn(y, x, 5.0000001201E-1f);
    y = __fmaf_rn(y, x2, x);
    y = __fadd_rn(y, 1.0f);
    int k = (int)fx;
    float scale = __int_as_float((k + 127) << 23);
    return fmaxf(__fmul_rn(y, scale), x_in);
}

__device__ __forceinline__ float xla_sigmoid(float x) {
    float e = xla_cpu_expf(-x);
    return __fdiv_rn(1.0f, __fadd_rn(1.0f, e));
}

__device__ __forceinline__ unsigned int fmap(float f) {
    unsigned int u = __float_as_uint(f);
    return (u & 0x80000000u) ? ~u : (u | 0x80000000u);
}
__device__ __forceinline__ float funmap(unsigned int m) {
    unsigned int u = (m & 0x80000000u) ? (m & 0x7FFFFFFFu) : ~m;
    return __uint_as_float(u);
}

__device__ __forceinline__ unsigned int redux_min_u32(unsigned int x) {
    unsigned int r;
    asm("redux.sync.min.u32 %0, %1, 0xffffffff;" : "=r"(r) : "r"(x));
    return r;
}

// packed f32x2 add: each 32-bit lane is an independent IEEE RN add (bit-exact)
__device__ __forceinline__ float2 addx2(float2 a, float2 b) {
    unsigned long long ua = *reinterpret_cast<unsigned long long*>(&a);
    unsigned long long ub = *reinterpret_cast<unsigned long long*>(&b);
    unsigned long long uc;
    asm("add.rn.f32x2 %0, %1, %2;" : "=l"(uc) : "l"(ua), "l"(ub));
    return *reinterpret_cast<float2*>(&uc);
}
__device__ __forceinline__ float2 f2b(float v) { float2 r; r.x = v; r.y = v; return r; }

__global__ __launch_bounds__(NT, 1)
void hungarian_kernel(const float* __restrict__ in0,
                      const float* __restrict__ in1,
                      float* __restrict__ out,
                      int write_col_ind) {
    __shared__ float  u_sh[KN + 1];
    __shared__ int    p_sh[QN1];
    __shared__ int    way_sh[QN1];
    __shared__ float  t1_sh[KN], t2_sh[KN];
    __shared__ float4 prow[QN1];
    __shared__ unsigned long long redk[2][NW];
    __shared__ float  hist_sh[QN1];       // per-step delta history
    __shared__ int    mark_sh[QN1];       // step index when column became used
    __shared__ int    a_sh[KN];
    __shared__ int    swap_flag;

    const int tid  = threadIdx.x;
    const int b    = blockIdx.x;
    const int lane = tid & 31;
    const int wid  = tid >> 5;

    if (tid == 0) {
        bool l0 = probe_is_labels(in0);
        bool l1 = probe_is_labels(in1);
        swap_flag = (l0 && !l1) ? 1 : 0;
    }
    __syncthreads();
    const float* L  = (swap_flag ? in1 : in0) + (size_t)b * NELEM;  // logits
    const float* Lb = (swap_flag ? in0 : in1) + (size_t)b * NELEM;  // labels

    // Per-thread columns jc = tid*CPT + c + 1, packed in pairs (x=even c, y=odd c)
    float2 negorig2[NPR], np2[NPR], b1p2[NPR], b2p2[NPR], nvr2[NPR], minv2[NPR];
    int    wayr[CPT];
    #pragma unroll
    for (int c = 0; c < CPT; c++) {
        int q = tid * CPT + c;
        float ng = -xla_sigmoid(L[q * 3 + 0]);
        float v1 = L[q * 3 + 1];
        float v2 = L[q * 3 + 2];
        if (c & 1) { negorig2[c >> 1].y = ng; b1p2[c >> 1].y = v1; b2p2[c >> 1].y = v2; }
        else       { negorig2[c >> 1].x = ng; b1p2[c >> 1].x = v1; b2p2[c >> 1].x = v2; }
    }
    #pragma unroll
    for (int p = 0; p < NPR; p++) nvr2[p] = f2b(0.0f);   // nvr = -v
    if (tid < KN) {
        t1_sh[tid] = Lb[tid * 3 + 1];
        t2_sh[tid] = Lb[tid * 3 + 2];
        u_sh[tid + 1] = 0.0f;
    }
    if (tid == 0) u_sh[0] = 0.0f;
    for (int idx = tid; idx < QN1; idx += NT) p_sh[idx] = 0;
    __syncthreads();

    for (int i = 1; i <= KN; i++) {
        // rebuild prow: p and u frozen during a path (proven R7)
        for (int idx = tid; idx < QN; idx += NT) {
            int jj = idx + 1;
            int pi = p_sh[jj];
            float4 r;
            r.x = __int_as_float(pi);
            if (pi > 0) { r.y = u_sh[pi]; r.z = t1_sh[pi - 1]; r.w = t2_sh[pi - 1]; }
            else        { r.y = 0.0f; r.z = 0.0f; r.w = 0.0f; }
            prow[jj] = r;
        }

        #pragma unroll
        for (int p = 0; p < NPR; p++) {
            minv2[p] = f2b(INFV);
            np2[p]   = negorig2[p];
        }
        #pragma unroll
        for (int c = 0; c < CPT; c++) wayr[c] = 0;
        unsigned int usedm = 0;
        int   j0 = 0;
        float ui0 = u_sh[i];
        float tt1 = t1_sh[i - 1], tt2 = t2_sh[i - 1];
        float2 ntt1p = f2b(-tt1), ntt2p = f2b(-tt2), nui0p = f2b(-ui0);
        int sidx = 0;
        int par = 0;

        while (true) {
            if (tid == 0) mark_sh[j0] = sidx;     // predicated STS
            // used-mark: poison np/minv halves of the owned column
            unsigned int t = (unsigned int)(j0 - 1 - tid * CPT);
            if (t < CPT) usedm |= (1u << t);
            #pragma unroll
            for (int p = 0; p < NPR; p++) {
                bool pdx = ((unsigned int)(2 * p)     == t);
                bool pdy = ((unsigned int)(2 * p + 1) == t);
                np2[p].x   = pdx ? FINF : np2[p].x;
                np2[p].y   = pdy ? FINF : np2[p].y;
                minv2[p].x = pdx ? FINF : minv2[p].x;
                minv2[p].y = pdy ? FINF : minv2[p].y;
            }

            // packed candidate chain: cur = ((np + s) - ui0) - vr, exact order
            #pragma unroll
            for (int p = 0; p < NPR; p++) {
                float2 d1 = addx2(b1p2[p], ntt1p);
                float2 d2 = addx2(b2p2[p], ntt2p);
                float2 sp;
                sp.x = __fadd_rn(fabsf(d1.x), fabsf(d2.x));
                sp.y = __fadd_rn(fabsf(d1.y), fabsf(d2.y));
                float2 q = addx2(np2[p], sp);
                q = addx2(q, nui0p);
                float2 cur = addx2(q, nvr2[p]);
                if (cur.x < minv2[p].x) wayr[2 * p]     = j0;
                if (cur.y < minv2[p].y) wayr[2 * p + 1] = j0;
                minv2[p].x = fminf(minv2[p].x, cur.x);
                minv2[p].y = fminf(minv2[p].y, cur.y);
            }
            // thread-best: exact min tree over 8 halves
            float m0 = fminf(minv2[0].x, minv2[0].y);
            float m1 = fminf(minv2[1].x, minv2[1].y);
            float m2 = fminf(minv2[2].x, minv2[2].y);
            float m3 = fminf(minv2[3].x, minv2[3].y);
            float bestv = fminf(fminf(m0, m1), fminf(m2, m3));
            // local argmin (first col); fills redux1 latency shadow
            unsigned int lj = 0x7FFFFFFFu;
            #pragma unroll
            for (int p = NPR - 1; p >= 0; p--) {
                if (minv2[p].y == bestv) lj = (unsigned int)(tid * CPT + 2 * p + 2);
                if (minv2[p].x == bestv) lj = (unsigned int)(tid * CPT + 2 * p + 1);
            }

            unsigned int mb   = fmap(bestv);
            unsigned int wmin = redux_min_u32(mb);
            unsigned int jc2  = (mb == wmin) ? lj : 0x7FFFFFFFu;
            unsigned int jmin = redux_min_u32(jc2);

            float4 pr = prow[jmin];   // speculative prefetch (prow frozen)

            if (lane == 0)
                redk[par][wid] = ((unsigned long long)wmin << 32) | jmin;
            __syncthreads();

            unsigned long long k0 = redk[par][0], k1 = redk[par][1];
            unsigned long long k2 = redk[par][2], k3 = redk[par][3];
            unsigned long long g = k0 < k1 ? k0 : k1;
            unsigned long long h = k2 < k3 ? k2 : k3;
            if (h < g) g = h;

            float delta = funmap((unsigned int)(g >> 32));
            int   j1    = (int)(unsigned int)g;
            if (j1 != (int)jmin) pr = prow[j1];   // warp-uniform fallback

            if (tid == 0) hist_sh[sidx] = delta;  // predicated STS
            sidx++;

            float2 ndp = f2b(-delta);             // minv -= delta (Inf stays Inf)
            #pragma unroll
            for (int p = 0; p < NPR; p++) minv2[p] = addx2(minv2[p], ndp);

            j0 = j1;
            int i0 = __float_as_int(pr.x);
            if (i0 == 0) break;                   // free column reached
            ui0 = pr.y; tt1 = pr.z; tt2 = pr.w;
            ntt1p = f2b(-tt1); ntt2p = f2b(-tt2); nui0p = f2b(-ui0);
            par ^= 1;
        }

        // ---- path end: deferred replay (bit-exact sequential adds) ----
        __syncthreads();    // hist/mark (incl. last step) visible to all
        int send = sidx;
        float uflush[CPT];
        int   urow[CPT];
        #pragma unroll
        for (int c = 0; c < CPT; c++) {
            if (usedm & (1u << c)) {
                int jc  = tid * CPT + c + 1;
                int ms  = mark_sh[jc];
                int i0r = p_sh[jc];
                float acc = u_sh[i0r];
                float nv  = (c & 1) ? nvr2[c >> 1].y : nvr2[c >> 1].x;
                for (int s = ms; s < send; s++) {
                    float d = hist_sh[s];
                    acc += d;      // u[p[j]] += delta, sequential (bit-exact)
                    nv  += d;      // v[j] -= delta  <=>  nv += delta (exact)
                }
                uflush[c] = acc; urow[c] = i0r;
                if (c & 1) nvr2[c >> 1].y = nv; else nvr2[c >> 1].x = nv;
            }
        }
        float acc0 = 0.0f;
        if (tid == 0) {          // column 0: all deltas onto u[i]
            acc0 = u_sh[i];
            for (int s = 0; s < send; s++) acc0 += hist_sh[s];
        }
        __syncthreads();         // all u_sh reads done before writes
        #pragma unroll
        for (int c = 0; c < CPT; c++) {
            way_sh[tid * CPT + c + 1] = wayr[c];
            if (usedm & (1u << c)) u_sh[urow[c]] = uflush[c];
        }
        if (tid == 0) u_sh[i] = acc0;
        __syncthreads();

        if (tid == 0) {          // augment
            int jj = j0;
            while (jj != 0) {
                int jn = way_sh[jj];
                p_sh[jj] = (jn == 0) ? i : p_sh[jn];
                jj = jn;
            }
        }
        __syncthreads();
    }

    // a[row] = column
    #pragma unroll
    for (int c = 0; c < CPT; c++) {
        int jc = tid * CPT + c + 1;
        int pv = p_sh[jc];
        if (pv > 0) a_sh[pv - 1] = jc - 1;
    }
    __syncthreads();

    // row_ind = sort(a), col_ind = argsort(a); output f32
    if (tid < KN) {
        int av = a_sh[tid];
        int rank = 0;
        #pragma unroll 8
        for (int m = 0; m < KN; m++) rank += (a_sh[m] < av);
        out[b * KN + rank] = (float)av;
        if (write_col_ind) out[BSN * KN + b * KN + rank] = (float)tid;
    }
}

extern "C" void kernel_launch(void* const* d_in, const int* in_sizes, int n_in,
                              void* d_out, int out_size) {
    const float* in0;
    const float* in1;
    if (n_in == 1) {
        in0 = (const float*)d_in[0];
        in1 = in0 + NELEM * BSN;
    } else {
        int i0 = -1, i1 = -1;
        for (int t = 0; t < n_in; t++) {
            if (in_sizes[t] == BSN * NELEM) {
                if (i0 < 0) i0 = t;
                else if (i1 < 0) i1 = t;
            }
        }
        if (i0 < 0) { i0 = 0; i1 = 1; }
        if (i1 < 0) i1 = (i0 == 0 ? 1 : 0);
        in0 = (const float*)d_in[i0];
        in1 = (const float*)d_in[i1];
    }
    float* out = (float*)d_out;
    int write_col = (out_size >= 2 * BSN * KN) ? 1 : 0;
    hungarian_kernel<<<BSN, NT>>>(in0, in1, out, write_col);
}

// round 14
// speedup vs baseline: 1.1686x; 1.1686x over previous
#include <cuda_runtime.h>
#include <cuda_bf16.h>
#include <math.h>

#define BSN 32
#define QN 1024
#define KN 96
#define QN1 (QN + 1)
#define INFV 1000000000.0f
#define NELEM (QN * 3)
#define NT 128
#define CPT 8
#define NPR (CPT / 2)
#define NW (NT / 32)
#define FINF __int_as_float(0x7F800000)

__device__ __forceinline__ bool probe_is_labels(const float* x) {
    const int qs[6] = {0, 13, 95, 96, 511, 1023};
    #pragma unroll
    for (int t = 0; t < 6; t++) {
        float v = x[qs[t] * 3];
        if (v != 0.0f && v != 1.0f) return false;
    }
    return true;
}

// Bit-exact replica of XLA:CPU GenerateVF32Exp (proven R6).
__device__ __forceinline__ float xla_cpu_expf(float x_in) {
    float x = fmaxf(fminf(x_in, 88.3762626647950f), -88.3762626647949f);
    float fx = floorf(__fmaf_rn(x, 1.44269504088896341f, 0.5f));
    float tmp = __fmul_rn(0.693359375f, fx);
    float z   = __fmul_rn(-2.12194440e-4f, fx);
    x = __fsub_rn(x, tmp);
    x = __fsub_rn(x, z);
    float x2 = __fmul_rn(x, x);
    float y = __fmaf_rn(x, 1.9875691500E-4f, 1.3981999507E-3f);
    y = __fmaf_rn(y, x, 8.3334519073E-3f);
    y = __fmaf_rn(y, x, 4.1665795894E-2f);
    y = __fmaf_rn(y, x, 1.6666665459E-1f);
    y = __fmaf_rn(y, x, 5.0000001201E-1f);
    y = __fmaf_rn(y, x2, x);
    y = __fadd_rn(y, 1.0f);
    int k = (int)fx;
    float scale = __int_as_float((k + 127) << 23);
    return fmaxf(__fmul_rn(y, scale), x_in);
}

__device__ __forceinline__ float xla_sigmoid(float x) {
    float e = xla_cpu_expf(-x);
    return __fdiv_rn(1.0f, __fadd_rn(1.0f, e));
}

__device__ __forceinline__ unsigned int fmap(float f) {
    unsigned int u = __float_as_uint(f);
    return (u & 0x80000000u) ? ~u : (u | 0x80000000u);
}
__device__ __forceinline__ float funmap(unsigned int m) {
    unsigned int u = (m & 0x80000000u) ? (m & 0x7FFFFFFFu) : ~m;
    return __uint_as_float(u);
}

__device__ __forceinline__ unsigned int redux_min_u32(unsigned int x) {
    unsigned int r;
    asm("redux.sync.min.u32 %0, %1, 0xffffffff;" : "=r"(r) : "r"(x));
    return r;
}

// packed f32x2 add: each 32-bit lane independent IEEE RN add (bit-exact)
__device__ __forceinline__ float2 addx2(float2 a, float2 b) {
    unsigned long long ua = *reinterpret_cast<unsigned long long*>(&a);
    unsigned long long ub = *reinterpret_cast<unsigned long long*>(&b);
    unsigned long long uc;
    asm("add.rn.f32x2 %0, %1, %2;" : "=l"(uc) : "l"(ua), "l"(ub));
    return *reinterpret_cast<float2*>(&uc);
}
__device__ __forceinline__ float2 f2b(float v) { float2 r; r.x = v; r.y = v; return r; }

__global__ __launch_bounds__(NT, 1)
void hungarian_kernel(const float* __restrict__ in0,
                      const float* __restrict__ in1,
                      float* __restrict__ out,
                      int write_col_ind) {
    __shared__ float  u_sh[KN + 1];
    __shared__ int    p_sh[QN1];
    __shared__ int    way_sh[QN1];
    __shared__ float  t1_sh[KN], t2_sh[KN];
    __shared__ float4 prow[QN1];
    __shared__ unsigned long long redk[2][NW];
    __shared__ int    a_sh[KN];
    __shared__ int    swap_flag;

    const int tid  = threadIdx.x;
    const int b    = blockIdx.x;
    const int lane = tid & 31;
    const int wid  = tid >> 5;

    if (tid == 0) {
        bool l0 = probe_is_labels(in0);
        bool l1 = probe_is_labels(in1);
        swap_flag = (l0 && !l1) ? 1 : 0;
    }
    __syncthreads();
    const float* L  = (swap_flag ? in1 : in0) + (size_t)b * NELEM;  // logits
    const float* Lb = (swap_flag ? in0 : in1) + (size_t)b * NELEM;  // labels

    // Per-thread columns jc = tid*CPT + c + 1, packed pairs (x=even c, y=odd c)
    float2 negorig2[NPR], np2[NPR], b1p2[NPR], b2p2[NPR], minv2[NPR];
    float  nvr[CPT], uacc[CPT];
    int    rowc[CPT], wayr[CPT];
    #pragma unroll
    for (int c = 0; c < CPT; c++) {
        int q = tid * CPT + c;
        float ng = -xla_sigmoid(L[q * 3 + 0]);
        float v1 = L[q * 3 + 1];
        float v2 = L[q * 3 + 2];
        if (c & 1) { negorig2[c >> 1].y = ng; b1p2[c >> 1].y = v1; b2p2[c >> 1].y = v2; }
        else       { negorig2[c >> 1].x = ng; b1p2[c >> 1].x = v1; b2p2[c >> 1].x = v2; }
        nvr[c] = 0.0f;     // nvr = -v (negation commutes with RN: bit-exact)
    }
    if (tid < KN) {
        t1_sh[tid] = Lb[tid * 3 + 1];
        t2_sh[tid] = Lb[tid * 3 + 2];
        u_sh[tid + 1] = 0.0f;
    }
    if (tid == 0) u_sh[0] = 0.0f;
    for (int idx = tid; idx < QN1; idx += NT) p_sh[idx] = 0;
    __syncthreads();

    for (int i = 1; i <= KN; i++) {
        // rebuild prow: p and u frozen during a path (proven R7)
        for (int idx = tid; idx < QN; idx += NT) {
            int jj = idx + 1;
            int pi = p_sh[jj];
            float4 r;
            r.x = __int_as_float(pi);
            if (pi > 0) { r.y = u_sh[pi]; r.z = t1_sh[pi - 1]; r.w = t2_sh[pi - 1]; }
            else        { r.y = 0.0f; r.z = 0.0f; r.w = 0.0f; }
            prow[jj] = r;
        }

        #pragma unroll
        for (int p = 0; p < NPR; p++) { minv2[p] = f2b(INFV); np2[p] = negorig2[p]; }
        #pragma unroll
        for (int c = 0; c < CPT; c++) { wayr[c] = 0; uacc[c] = 0.0f; rowc[c] = 0; }
        unsigned int usedm = 0;
        int   j0 = 0, i0 = i;
        float ui0 = u_sh[i];
        float tt1 = t1_sh[i - 1], tt2 = t2_sh[i - 1];
        float2 ntt1p = f2b(-tt1), ntt2p = f2b(-tt2), nui0p = f2b(-ui0);
        float u0acc = ui0;     // identical across threads; tid 0's store used
        int par = 0;

        while (true) {
            // branchless used-mark
            unsigned int t = (unsigned int)(j0 - 1 - tid * CPT);
            if (t < CPT) usedm |= (1u << t);
            #pragma unroll
            for (int p = 0; p < NPR; p++) {
                bool pdx = ((unsigned int)(2 * p)     == t);
                bool pdy = ((unsigned int)(2 * p + 1) == t);
                np2[p].x   = pdx ? FINF : np2[p].x;
                np2[p].y   = pdy ? FINF : np2[p].y;
                minv2[p].x = pdx ? FINF : minv2[p].x;
                minv2[p].y = pdy ? FINF : minv2[p].y;
            }
            #pragma unroll
            for (int c = 0; c < CPT; c++) {
                bool pd = ((unsigned int)c == t);
                uacc[c] = pd ? ui0 : uacc[c];
                rowc[c] = pd ? i0  : rowc[c];
            }

            // packed candidate chain: cur = ((np + s) - ui0) - v, exact order
            #pragma unroll
            for (int p = 0; p < NPR; p++) {
                float2 d1 = addx2(b1p2[p], ntt1p);
                float2 d2 = addx2(b2p2[p], ntt2p);
                float2 sp;
                sp.x = __fadd_rn(fabsf(d1.x), fabsf(d2.x));
                sp.y = __fadd_rn(fabsf(d1.y), fabsf(d2.y));
                float2 q = addx2(np2[p], sp);
                q = addx2(q, nui0p);
                float2 cur;
                cur.x = __fadd_rn(q.x, nvr[2 * p]);
                cur.y = __fadd_rn(q.y, nvr[2 * p + 1]);
                if (cur.x < minv2[p].x) wayr[2 * p]     = j0;
                if (cur.y < minv2[p].y) wayr[2 * p + 1] = j0;
                minv2[p].x = fminf(minv2[p].x, cur.x);
                minv2[p].y = fminf(minv2[p].y, cur.y);
            }
            // thread-best: exact min tree
            float m0 = fminf(minv2[0].x, minv2[0].y);
            float m1 = fminf(minv2[1].x, minv2[1].y);
            float m2 = fminf(minv2[2].x, minv2[2].y);
            float m3 = fminf(minv2[3].x, minv2[3].y);
            float bestv = fminf(fminf(m0, m1), fminf(m2, m3));
            // local argmin (first col), off the inter-redux critical path
            unsigned int lj = 0x7FFFFFFFu;
            #pragma unroll
            for (int p = NPR - 1; p >= 0; p--) {
                if (minv2[p].y == bestv) lj = (unsigned int)(tid * CPT + 2 * p + 2);
                if (minv2[p].x == bestv) lj = (unsigned int)(tid * CPT + 2 * p + 1);
            }

            unsigned int mb   = fmap(bestv);
            unsigned int wmin = redux_min_u32(mb);
            unsigned int jc2  = (mb == wmin) ? lj : 0x7FFFFFFFu;
            unsigned int jmin = redux_min_u32(jc2);

            float4 pr = prow[jmin];   // speculative prefetch (prow frozen)

            if (lane == 0)
                redk[par][wid] = ((unsigned long long)wmin << 32) | jmin;
            __syncthreads();

            unsigned long long k0 = redk[par][0], k1 = redk[par][1];
            unsigned long long k2 = redk[par][2], k3 = redk[par][3];
            unsigned long long g = k0 < k1 ? k0 : k1;
            unsigned long long h = k2 < k3 ? k2 : k3;
            if (h < g) g = h;

            float delta = funmap((unsigned int)(g >> 32));
            int   j1    = (int)(unsigned int)g;
            if (j1 != (int)jmin) pr = prow[j1];   // warp-uniform fallback

            // updates: packed minv -= delta (Inf stays Inf); scalar predicated u/v
            float2 ndp = f2b(-delta);
            #pragma unroll
            for (int p = 0; p < NPR; p++) minv2[p] = addx2(minv2[p], ndp);
            #pragma unroll
            for (int c = 0; c < CPT; c++) {
                if (usedm & (1u << c)) { uacc[c] += delta; nvr[c] += delta; }
            }
            u0acc += delta;    // all threads, branchless

            j0 = j1;
            i0 = __float_as_int(pr.x);
            if (i0 == 0) break;        // free column reached
            ui0 = pr.y; tt1 = pr.z; tt2 = pr.w;
            ntt1p = f2b(-tt1); ntt2p = f2b(-tt2); nui0p = f2b(-ui0);
            par ^= 1;
        }

        // flush u and way (register-accumulated; exact sequential values)
        #pragma unroll
        for (int c = 0; c < CPT; c++) {
            way_sh[tid * CPT + c + 1] = wayr[c];
            if (usedm & (1u << c)) u_sh[rowc[c]] = uacc[c];
        }
        if (tid == 0) u_sh[i] = u0acc;
        __syncthreads();

        if (tid == 0) {                 // augment
            int jj = j0;
            while (jj != 0) {
                int jn = way_sh[jj];
                p_sh[jj] = (jn == 0) ? i : p_sh[jn];
                jj = jn;
            }
        }
        __syncthreads();
    }

    // a[row] = column
    #pragma unroll
    for (int c = 0; c < CPT; c++) {
        int jc = tid * CPT + c + 1;
        int pv = p_sh[jc];
        if (pv > 0) a_sh[pv - 1] = jc - 1;
    }
    __syncthreads();

    // row_ind = sort(a), col_ind = argsort(a); output f32
    if (tid < KN) {
        int av = a_sh[tid];
        int rank = 0;
        #pragma unroll 8
        for (int m = 0; m < KN; m++) rank += (a_sh[m] < av);
        out[b * KN + rank] = (float)av;
        if (write_col_ind) out[BSN * KN + b * KN + rank] = (float)tid;
    }
}

extern "C" void kernel_launch(void* const* d_in, const int* in_sizes, int n_in,
                              void* d_out, int out_size) {
    const float* in0;
    const float* in1;
    if (n_in == 1) {
        in0 = (const float*)d_in[0];
        in1 = in0 + NELEM * BSN;
    } else {
        int i0 = -1, i1 = -1;
        for (int t = 0; t < n_in; t++) {
            if (in_sizes[t] == BSN * NELEM) {
                if (i0 < 0) i0 = t;
                else if (i1 < 0) i1 = t;
            }
        }
        if (i0 < 0) { i0 = 0; i1 = 1; }
        if (i1 < 0) i1 = (i0 == 0 ? 1 : 0);
        in0 = (const float*)d_in[i0];
        in1 = (const float*)d_in[i1];
    }
    float* out = (float*)d_out;
    int write_col = (out_size >= 2 * BSN * KN) ? 1 : 0;
    hungarian_kernel<<<BSN, NT>>>(in0, in1, out, write_col);
}